// round 1
// baseline (speedup 1.0000x reference)
#include <cuda_runtime.h>

// Problem constants (dataset-fixed)
#define HDIM   256
#define PPH    16
#define KOCC   8
#define KSUBJ  16
#define NBIN   128          // P * K_OCC global occurrence classes
#define CAP    2048         // per-bin capacity (mean 1024, binomial tail @2048 ~ impossible)
#define MT     128          // rows per CTA tile
#define NCOL   40           // 16 phase + 8 occ + 16 subj logits

// Scratch (no cudaMalloc allowed)
__device__ int g_cursor[NBIN];
__device__ int g_sorted[NBIN * CAP];

// ---------------------------------------------------------------------------
__global__ void k_zero() {
    if (threadIdx.x < NBIN) g_cursor[threadIdx.x] = 0;
}

// Bin rows by global occurrence id with smem-aggregated histogram:
// one global atomic per (CTA, bin) instead of one per row.
__global__ __launch_bounds__(256) void k_scatter(const int* __restrict__ xp,
                                                 const int* __restrict__ xo, int n) {
    __shared__ int hcnt[NBIN];
    __shared__ int hbase[NBIN];
    int t = threadIdx.x;
    if (t < NBIN) hcnt[t] = 0;
    __syncthreads();

    int base = blockIdx.x * 1024;
    int occ[4], pos[4];
#pragma unroll
    for (int j = 0; j < 4; j++) {
        int i = base + j * 256 + t;
        if (i < n) {
            occ[j] = xp[i] * KOCC + xo[i];
            pos[j] = atomicAdd(&hcnt[occ[j]], 1);
        } else {
            occ[j] = -1;
        }
    }
    __syncthreads();
    if (t < NBIN && hcnt[t] > 0) hbase[t] = atomicAdd(&g_cursor[t], hcnt[t]);
    __syncthreads();
#pragma unroll
    for (int j = 0; j < 4; j++) {
        if (occ[j] >= 0) {
            int p = hbase[occ[j]] + pos[j];
            if (p < CAP) g_sorted[occ[j] * CAP + p] = base + j * 256 + t;
        }
    }
}

// Packed fp32x2 FMA (ptxas never auto-fuses this; PTX-only path, 2x FFMA rate)
__device__ __forceinline__ void fma2(unsigned long long& d, unsigned long long a,
                                     unsigned long long b) {
    asm("fma.rn.f32x2 %0, %1, %2, %0;" : "+l"(d) : "l"(a), "l"(b));
}

// ---------------------------------------------------------------------------
// Main: per-bin dense GEMM [MT,256] x [256,40] + 3-group softmax epilogue.
// Thread tile: 4 rows x 5 cols, accumulators packed (even-k, odd-k) in f32x2.
__global__ __launch_bounds__(256, 2) void k_main(
    const float* __restrict__ X,
    const float* __restrict__ Wp, const float* __restrict__ bp,
    const float* __restrict__ Wo, const float* __restrict__ bo,
    const float* __restrict__ Ws, const float* __restrict__ bs2,
    const int* __restrict__ subj, float* __restrict__ out, int n)
{
    // sbuf carve: xs = [0,1032) float4  ([kq 0..7][row 0..127], stride 129 to kill
    //             bank conflicts), ws = [1032, 1352) float4 ([col][kq]).
    // Epilogue aliases the whole thing as logits [MT][41] (5246 floats <= 5408).
    __shared__ float4 sbuf[1352];
    __shared__ int    rowidx[MT];
    __shared__ float  biasz[48];

    int bin  = blockIdx.x;
    int cnt  = g_cursor[bin];
    int base = blockIdx.y * MT;
    if (base >= cnt) return;
    int nrows = min(MT, cnt - base);
    int phase = bin >> 3, occl = bin & 7;
    int t = threadIdx.x;

    if (t < MT)
        rowidx[t] = g_sorted[bin * CAP + base + ((t < nrows) ? t : 0)];
    if (t < NCOL)
        biasz[t] = (t < 16) ? bp[t]
                 : (t < 24) ? bo[phase * KOCC + (t - 16)]
                            : bs2[bin * KSUBJ + (t - 24)];
    __syncthreads();

    // --- loader setup ------------------------------------------------------
    int kq = t & 7, rr = t >> 3;   // X loader: 4 rows per thread at kq-th float4
    const float4* xg0 = (const float4*)(X + (size_t)rowidx[rr     ] * HDIM) + kq;
    const float4* xg1 = (const float4*)(X + (size_t)rowidx[rr + 32] * HDIM) + kq;
    const float4* xg2 = (const float4*)(X + (size_t)rowidx[rr + 64] * HDIM) + kq;
    const float4* xg3 = (const float4*)(X + (size_t)rowidx[rr + 96] * HDIM) + kq;

    auto wrow = [&](int col) -> const float4* {
        const float* p;
        if (col < 16)      p = Wp + col * HDIM;
        else if (col < 24) p = Wo + (phase * KOCC + col - 16) * HDIM;
        else               p = Ws + (bin * KSUBJ + col - 24) * HDIM;
        return (const float4*)p;
    };
    const float4* wg0 = wrow(t >> 3) + (t & 7);                 // cols 0..31
    const float4* wg1 = (t < 64) ? (wrow((256 + t) >> 3) + (t & 7)) : xg0; // cols 32..39

    // --- compute setup -----------------------------------------------------
    int lane = t & 31, wrp = t >> 5;   // warp -> cols [5*wrp, 5*wrp+5)
    unsigned long long acc[4][5];
#pragma unroll
    for (int i = 0; i < 4; i++)
#pragma unroll
        for (int c = 0; c < 5; c++) acc[i][c] = 0ull;

    float4* xs = sbuf;
    float4* ws = sbuf + 1032;
    const ulonglong2* xsu = (const ulonglong2*)sbuf;
    const ulonglong2* wsu = (const ulonglong2*)(sbuf + 1032);

    for (int kc = 0; kc < HDIM / 32; kc++) {
        float4 xv0 = xg0[kc * 8], xv1 = xg1[kc * 8];
        float4 xv2 = xg2[kc * 8], xv3 = xg3[kc * 8];
        float4 wv0 = wg0[kc * 8];
        float4 wv1;
        if (t < 64) wv1 = wg1[kc * 8];

        __syncthreads();   // prior chunk's readers done
        xs[kq * 129 + rr     ] = xv0;
        xs[kq * 129 + rr + 32] = xv1;
        xs[kq * 129 + rr + 64] = xv2;
        xs[kq * 129 + rr + 96] = xv3;
        ws[t] = wv0;
        if (t < 64) ws[256 + t] = wv1;
        __syncthreads();

#pragma unroll
        for (int kk = 0; kk < 8; kk++) {
            ulonglong2 a0 = xsu[kk * 129 + lane     ];
            ulonglong2 a1 = xsu[kk * 129 + lane + 32];
            ulonglong2 a2 = xsu[kk * 129 + lane + 64];
            ulonglong2 a3 = xsu[kk * 129 + lane + 96];
#pragma unroll
            for (int c = 0; c < 5; c++) {
                ulonglong2 wv = wsu[(5 * wrp + c) * 8 + kk];   // warp-broadcast
                fma2(acc[0][c], a0.x, wv.x); fma2(acc[0][c], a0.y, wv.y);
                fma2(acc[1][c], a1.x, wv.x); fma2(acc[1][c], a1.y, wv.y);
                fma2(acc[2][c], a2.x, wv.x); fma2(acc[2][c], a2.y, wv.y);
                fma2(acc[3][c], a3.x, wv.x); fma2(acc[3][c], a3.y, wv.y);
            }
        }
    }

    // --- epilogue: stage logits, per-row 3-group softmax -------------------
    __syncthreads();
    float* lg = (float*)sbuf;   // [MT][41]
#pragma unroll
    for (int i = 0; i < 4; i++)
#pragma unroll
        for (int c = 0; c < 5; c++) {
            unsigned long long v = acc[i][c];
            float s = __int_as_float((int)(unsigned int)v) +
                      __int_as_float((int)(v >> 32));
            lg[(lane + 32 * i) * 41 + (5 * wrp + c)] = s + biasz[5 * wrp + c];
        }
    __syncthreads();

    if (t < nrows) {
        const float* L = lg + t * 41;
        int orig = rowidx[t];

        float m1 = L[0];
#pragma unroll
        for (int j = 1; j < 16; j++) m1 = fmaxf(m1, L[j]);
        float s1 = 0.f;
#pragma unroll
        for (int j = 0; j < 16; j++) s1 += expf(L[j] - m1);
        float p1 = expf(L[phase] - m1) / s1;

        float m2 = L[16];
#pragma unroll
        for (int j = 17; j < 24; j++) m2 = fmaxf(m2, L[j]);
        float s2 = 0.f;
#pragma unroll
        for (int j = 16; j < 24; j++) s2 += expf(L[j] - m2);
        float p2 = expf(L[16 + occl] - m2) / s2;

        int sj = subj[orig];
        float m3 = L[24];
#pragma unroll
        for (int j = 25; j < 40; j++) m3 = fmaxf(m3, L[j]);
        float s3 = 0.f;
#pragma unroll
        for (int j = 24; j < 40; j++) s3 += expf(L[j] - m3);
        float p3 = expf(L[24 + sj] - m3) / s3;

        float po = p1 * p2;
        out[orig]         = p1;
        out[n + orig]     = po;
        out[2 * n + orig] = po * p3;
    }
}

// ---------------------------------------------------------------------------
extern "C" void kernel_launch(void* const* d_in, const int* in_sizes, int n_in,
                              void* d_out, int out_size) {
    const float* X  = (const float*)d_in[0];
    const float* Wp = (const float*)d_in[1];
    const float* bp = (const float*)d_in[2];
    const float* Wo = (const float*)d_in[3];
    const float* bo = (const float*)d_in[4];
    const float* Ws = (const float*)d_in[5];
    const float* bs = (const float*)d_in[6];
    const int*   xp = (const int*)d_in[7];
    const int*   xo = (const int*)d_in[8];
    const int*   xs = (const int*)d_in[9];
    int n = in_sizes[0] / HDIM;
    float* out = (float*)d_out;

    k_zero<<<1, 128>>>();
    k_scatter<<<(n + 1023) / 1024, 256>>>(xp, xo, n);
    dim3 grid(NBIN, CAP / MT);
    k_main<<<grid, 256>>>(X, Wp, bp, Wo, bo, Ws, bs, xs, out, n);
}

// round 2
// speedup vs baseline: 1.0898x; 1.0898x over previous
#include <cuda_runtime.h>

// Problem constants (dataset-fixed)
#define HDIM   256
#define PPH    16
#define KOCC   8
#define KSUBJ  16
#define NBIN   128          // P * K_OCC global occurrence classes
#define CAP    2048         // per-bin capacity (mean 1024, binomial tail @2048 ~ impossible)
#define MT     128          // rows per CTA tile
#define NCOL   40           // 16 phase + 8 occ + 16 subj logits

// Scratch (no cudaMalloc allowed)
__device__ int g_cursor[NBIN];
__device__ int g_sorted[NBIN * CAP];

// ---------------------------------------------------------------------------
__global__ void k_zero() {
    if (threadIdx.x < NBIN) g_cursor[threadIdx.x] = 0;
}

// Bin rows by global occurrence id with smem-aggregated histogram:
// one global atomic per (CTA, bin) instead of one per row.
__global__ __launch_bounds__(256) void k_scatter(const int* __restrict__ xp,
                                                 const int* __restrict__ xo, int n) {
    __shared__ int hcnt[NBIN];
    __shared__ int hbase[NBIN];
    int t = threadIdx.x;
    if (t < NBIN) hcnt[t] = 0;
    __syncthreads();

    int base = blockIdx.x * 1024;
    int occ[4], pos[4];
#pragma unroll
    for (int j = 0; j < 4; j++) {
        int i = base + j * 256 + t;
        if (i < n) {
            occ[j] = xp[i] * KOCC + xo[i];
            pos[j] = atomicAdd(&hcnt[occ[j]], 1);
        } else {
            occ[j] = -1;
        }
    }
    __syncthreads();
    if (t < NBIN && hcnt[t] > 0) hbase[t] = atomicAdd(&g_cursor[t], hcnt[t]);
    __syncthreads();
#pragma unroll
    for (int j = 0; j < 4; j++) {
        if (occ[j] >= 0) {
            int p = hbase[occ[j]] + pos[j];
            if (p < CAP) g_sorted[occ[j] * CAP + p] = base + j * 256 + t;
        }
    }
}

// Packed fp32x2 FMA (ptxas never auto-fuses this; PTX-only path, 2x FFMA rate)
__device__ __forceinline__ void fma2(unsigned long long& d, unsigned long long a,
                                     unsigned long long b) {
    asm("fma.rn.f32x2 %0, %1, %2, %0;" : "+l"(d) : "l"(a), "l"(b));
}

// ---------------------------------------------------------------------------
// Main: per-bin dense GEMM [MT,256] x [256,40] + 3-group softmax epilogue.
// Thread tile: 4 rows x 5 cols, accumulators packed (even-k, odd-k) in f32x2.
// 2-stage software pipeline: prefetch(kc+2) / stage(kc+1) / compute(kc), one
// barrier per chunk, so DRAM latency is covered by a full chunk of compute.
__global__ __launch_bounds__(256, 2) void k_main(
    const float* __restrict__ X,
    const float* __restrict__ Wp, const float* __restrict__ bp,
    const float* __restrict__ Wo, const float* __restrict__ bo,
    const float* __restrict__ Ws, const float* __restrict__ bs2,
    const int* __restrict__ subj, float* __restrict__ out, int n)
{
    // Two stages of: xs = [0,1032) float4 ([kq 0..7][row 0..127], stride 129),
    //                ws = [1032,1352) float4 ([col][kq]).
    // Epilogue aliases the buffer as logits [MT][41] (5248 floats, fits easily).
    __shared__ float4 sbuf[2 * 1352];
    __shared__ int    rowidx[MT];
    __shared__ float  biasz[48];

    int bin  = blockIdx.x;
    int cnt  = g_cursor[bin];
    int base = blockIdx.y * MT;
    if (base >= cnt) return;
    int nrows = min(MT, cnt - base);
    int phase = bin >> 3, occl = bin & 7;
    int t = threadIdx.x;

    if (t < MT)
        rowidx[t] = g_sorted[bin * CAP + base + ((t < nrows) ? t : 0)];
    if (t < NCOL)
        biasz[t] = (t < 16) ? bp[t]
                 : (t < 24) ? bo[phase * KOCC + (t - 16)]
                            : bs2[bin * KSUBJ + (t - 24)];
    __syncthreads();

    // --- loader setup ------------------------------------------------------
    const int kq = t & 7, rr = t >> 3;   // X loader: 4 rows/thread at kq-th float4
    const float4* xg0 = (const float4*)(X + (size_t)rowidx[rr     ] * HDIM) + kq;
    const float4* xg1 = (const float4*)(X + (size_t)rowidx[rr + 32] * HDIM) + kq;
    const float4* xg2 = (const float4*)(X + (size_t)rowidx[rr + 64] * HDIM) + kq;
    const float4* xg3 = (const float4*)(X + (size_t)rowidx[rr + 96] * HDIM) + kq;

    auto wrow = [&](int col) -> const float4* {
        const float* p;
        if (col < 16)      p = Wp + col * HDIM;
        else if (col < 24) p = Wo + (phase * KOCC + col - 16) * HDIM;
        else               p = Ws + (bin * KSUBJ + col - 24) * HDIM;
        return (const float4*)p;
    };
    const float4* wg0 = wrow(t >> 3) + (t & 7);                              // cols 0..31
    const float4* wg1 = (t < 64) ? (wrow((256 + t) >> 3) + (t & 7)) : xg0;   // cols 32..39

    // --- compute setup -----------------------------------------------------
    int lane = t & 31, wrp = t >> 5;   // warp -> cols [5*wrp, 5*wrp+5)
    unsigned long long acc[4][5];
#pragma unroll
    for (int i = 0; i < 4; i++)
#pragma unroll
        for (int c = 0; c < 5; c++) acc[i][c] = 0ull;

    float4 px0, px1, px2, px3, pw0, pw1;

    auto ldchunk = [&](int kc) {
        px0 = xg0[kc * 8]; px1 = xg1[kc * 8];
        px2 = xg2[kc * 8]; px3 = xg3[kc * 8];
        pw0 = wg0[kc * 8];
        if (t < 64) pw1 = wg1[kc * 8];
    };
    auto stage = [&](int b) {
        float4* xs = sbuf + b * 1352;
        float4* ws = xs + 1032;
        xs[kq * 129 + rr     ] = px0;
        xs[kq * 129 + rr + 32] = px1;
        xs[kq * 129 + rr + 64] = px2;
        xs[kq * 129 + rr + 96] = px3;
        ws[t] = pw0;
        if (t < 64) ws[256 + t] = pw1;
    };

    ldchunk(0);
    stage(0);
    ldchunk(1);
    __syncthreads();

    for (int kc = 0; kc < HDIM / 32; kc++) {
        int b = kc & 1;
        const ulonglong2* xsu = (const ulonglong2*)(sbuf + b * 1352);
        const ulonglong2* wsu = xsu + 1032;

#pragma unroll
        for (int kk = 0; kk < 8; kk++) {
            ulonglong2 a0 = xsu[kk * 129 + lane     ];
            ulonglong2 a1 = xsu[kk * 129 + lane + 32];
            ulonglong2 a2 = xsu[kk * 129 + lane + 64];
            ulonglong2 a3 = xsu[kk * 129 + lane + 96];
#pragma unroll
            for (int c = 0; c < 5; c++) {
                ulonglong2 wv = wsu[(5 * wrp + c) * 8 + kk];   // warp-broadcast
                fma2(acc[0][c], a0.x, wv.x); fma2(acc[0][c], a0.y, wv.y);
                fma2(acc[1][c], a1.x, wv.x); fma2(acc[1][c], a1.y, wv.y);
                fma2(acc[2][c], a2.x, wv.x); fma2(acc[2][c], a2.y, wv.y);
                fma2(acc[3][c], a3.x, wv.x); fma2(acc[3][c], a3.y, wv.y);
            }
        }

        if (kc < 7) {
            stage(1 - b);                 // store prefetched chunk kc+1
            if (kc < 6) ldchunk(kc + 2);  // issue gmem loads for chunk kc+2
        }
        __syncthreads();
    }

    // --- epilogue: stage logits, per-row 3-group softmax -------------------
    float* lg = (float*)sbuf;   // [MT][41]
#pragma unroll
    for (int i = 0; i < 4; i++)
#pragma unroll
        for (int c = 0; c < 5; c++) {
            unsigned long long v = acc[i][c];
            float s = __int_as_float((int)(unsigned int)v) +
                      __int_as_float((int)(v >> 32));
            lg[(lane + 32 * i) * 41 + (5 * wrp + c)] = s + biasz[5 * wrp + c];
        }
    __syncthreads();

    if (t < nrows) {
        const float* L = lg + t * 41;
        int orig = rowidx[t];

        float m1 = L[0];
#pragma unroll
        for (int j = 1; j < 16; j++) m1 = fmaxf(m1, L[j]);
        float s1 = 0.f;
#pragma unroll
        for (int j = 0; j < 16; j++) s1 += expf(L[j] - m1);
        float p1 = expf(L[phase] - m1) / s1;

        float m2 = L[16];
#pragma unroll
        for (int j = 17; j < 24; j++) m2 = fmaxf(m2, L[j]);
        float s2 = 0.f;
#pragma unroll
        for (int j = 16; j < 24; j++) s2 += expf(L[j] - m2);
        float p2 = expf(L[16 + occl] - m2) / s2;

        int sj = subj[orig];
        float m3 = L[24];
#pragma unroll
        for (int j = 25; j < 40; j++) m3 = fmaxf(m3, L[j]);
        float s3 = 0.f;
#pragma unroll
        for (int j = 24; j < 40; j++) s3 += expf(L[j] - m3);
        float p3 = expf(L[24 + sj] - m3) / s3;

        float po = p1 * p2;
        out[orig]         = p1;
        out[n + orig]     = po;
        out[2 * n + orig] = po * p3;
    }
}

// ---------------------------------------------------------------------------
extern "C" void kernel_launch(void* const* d_in, const int* in_sizes, int n_in,
                              void* d_out, int out_size) {
    const float* X  = (const float*)d_in[0];
    const float* Wp = (const float*)d_in[1];
    const float* bp = (const float*)d_in[2];
    const float* Wo = (const float*)d_in[3];
    const float* bo = (const float*)d_in[4];
    const float* Ws = (const float*)d_in[5];
    const float* bs = (const float*)d_in[6];
    const int*   xp = (const int*)d_in[7];
    const int*   xo = (const int*)d_in[8];
    const int*   xs = (const int*)d_in[9];
    int n = in_sizes[0] / HDIM;
    float* out = (float*)d_out;

    k_zero<<<1, 128>>>();
    k_scatter<<<(n + 1023) / 1024, 256>>>(xp, xo, n);
    dim3 grid(NBIN, CAP / MT);
    k_main<<<grid, 256>>>(X, Wp, bp, Wo, bo, Ws, bs, xs, out, n);
}

// round 4
// speedup vs baseline: 1.4444x; 1.3254x over previous
#include <cuda_runtime.h>
#include <cuda_bf16.h>
#include <cstdint>

// Problem constants (dataset-fixed)
#define HDIM   256
#define KOCC   8
#define KSUBJ  16
#define NBIN   128
#define CAP    2048
#define MT     128          // rows per CTA tile
#define NCOL   40           // logit cols = 5 mma n8-tiles exactly

// smem layout (uint32 offsets into dynamic smem)
#define SA      20                       // A row stride (uint32), 20 % 8 == 4 -> conflict-free
#define AW      (128 * SA)               // words per A buffer component (2560)
#define SB      132                      // B col stride (uint32), 132 % 8 == 4
#define A_H0    0
#define A_H1    AW
#define A_L0    (2 * AW)
#define A_L1    (3 * AW)
#define B_H     (4 * AW)                 // 10240
#define B_L     (B_H + NCOL * SB)        // + 5280
#define DSM_WORDS (B_L + NCOL * SB)      // 20800 words = 83200 B

__device__ int g_cursor[NBIN];
__device__ int g_sorted[NBIN * CAP];

// ---------------------------------------------------------------------------
__global__ void k_zero() {
    if (threadIdx.x < NBIN) g_cursor[threadIdx.x] = 0;
}

__global__ __launch_bounds__(256) void k_scatter(const int* __restrict__ xp,
                                                 const int* __restrict__ xo, int n) {
    __shared__ int hcnt[NBIN];
    __shared__ int hbase[NBIN];
    int t = threadIdx.x;
    if (t < NBIN) hcnt[t] = 0;
    __syncthreads();
    int base = blockIdx.x * 1024;
    int occ[4], pos[4];
#pragma unroll
    for (int j = 0; j < 4; j++) {
        int i = base + j * 256 + t;
        if (i < n) { occ[j] = xp[i] * KOCC + xo[i]; pos[j] = atomicAdd(&hcnt[occ[j]], 1); }
        else occ[j] = -1;
    }
    __syncthreads();
    if (t < NBIN && hcnt[t] > 0) hbase[t] = atomicAdd(&g_cursor[t], hcnt[t]);
    __syncthreads();
#pragma unroll
    for (int j = 0; j < 4; j++)
        if (occ[j] >= 0) {
            int p = hbase[occ[j]] + pos[j];
            if (p < CAP) g_sorted[occ[j] * CAP + p] = base + j * 256 + t;
        }
}

// ---------------------------------------------------------------------------
// fp32 pair -> bf16x2 (hi) + bf16x2 (lo residual).  Lower 16 bits = first elem.
__device__ __forceinline__ void split2(float a, float b, uint32_t& hi, uint32_t& lo) {
    asm("cvt.rn.bf16x2.f32 %0, %1, %2;" : "=r"(hi) : "f"(b), "f"(a));
    float ha = __uint_as_float(hi << 16);
    float hb = __uint_as_float(hi & 0xffff0000u);
    float ra = a - ha, rb = b - hb;
    asm("cvt.rn.bf16x2.f32 %0, %1, %2;" : "=r"(lo) : "f"(rb), "f"(ra));
}

__device__ __forceinline__ void mma16816(float& d0, float& d1, float& d2, float& d3,
                                         uint32_t a0, uint32_t a1, uint32_t a2, uint32_t a3,
                                         uint32_t b0, uint32_t b1) {
    asm volatile(
        "mma.sync.aligned.m16n8k16.row.col.f32.bf16.bf16.f32 "
        "{%0,%1,%2,%3}, {%4,%5,%6,%7}, {%8,%9}, {%0,%1,%2,%3};"
        : "+f"(d0), "+f"(d1), "+f"(d2), "+f"(d3)
        : "r"(a0), "r"(a1), "r"(a2), "r"(a3), "r"(b0), "r"(b1));
}

// ---------------------------------------------------------------------------
__global__ __launch_bounds__(256, 2) void k_main(
    const float* __restrict__ X,
    const float* __restrict__ Wp, const float* __restrict__ bp,
    const float* __restrict__ Wo, const float* __restrict__ bo,
    const float* __restrict__ Ws, const float* __restrict__ bs2,
    const int* __restrict__ subj, float* __restrict__ out, int n)
{
    __shared__ int   rowidx[MT];
    __shared__ float biasz[NCOL];
    extern __shared__ uint32_t sm[];

    int bin  = blockIdx.x;
    int cnt  = g_cursor[bin];
    int base = blockIdx.y * MT;
    if (base >= cnt) return;
    int nrows = min(MT, cnt - base);
    int phase = bin >> 3, occl = bin & 7;
    int t = threadIdx.x, lane = t & 31, w = t >> 5;
    int g = lane >> 2, tig = lane & 3;

    if (t < MT)
        rowidx[t] = g_sorted[bin * CAP + base + ((t < nrows) ? t : 0)];
    if (t < NCOL)
        biasz[t] = (t < 16) ? bp[t]
                 : (t < 24) ? bo[phase * KOCC + (t - 16)]
                            : bs2[bin * KSUBJ + (t - 24)];
    __syncthreads();

    auto wrow = [&](int col) -> const float* {
        if (col < 16)      return Wp + col * HDIM;
        else if (col < 24) return Wo + (phase * KOCC + col - 16) * HDIM;
        else               return Ws + (bin * KSUBJ + col - 24) * HDIM;
    };

    // ---- stage full B panel (40 x 256) as bf16 hi/lo, stride SB ----------
#pragma unroll
    for (int j = 0; j < 20; j++) {
        int u   = t + j * 256;            // 0..5119
        int col = u >> 7, kp = u & 127;
        float2 wv = ((const float2*)wrow(col))[kp];
        uint32_t h, l;
        split2(wv.x, wv.y, h, l);
        sm[B_H + col * SB + kp] = h;
        sm[B_L + col * SB + kp] = l;
    }

    // ---- A pipeline: chunk = 32 k (16 kpairs), double-buffered ------------
    const int prow = t >> 1;                           // producer row
    const float4* xgp = (const float4*)(X + (size_t)rowidx[prow] * HDIM) + (t & 1) * 4;
    float4 pf[4];

    auto ldchunk = [&](int c) {
#pragma unroll
        for (int j = 0; j < 4; j++) pf[j] = xgp[c * 8 + j];
    };
    auto stage = [&](int b) {
        uint32_t hbase = (b ? A_H1 : A_H0) + prow * SA;
        uint32_t lbase = (b ? A_L1 : A_L0) + prow * SA;
        int f0 = (t & 1) * 4;
#pragma unroll
        for (int j = 0; j < 4; j++) {
            uint32_t h0, l0, h1, l1;
            split2(pf[j].x, pf[j].y, h0, l0);
            split2(pf[j].z, pf[j].w, h1, l1);
            int kp = (f0 + j) * 2;
            sm[hbase + kp] = h0; sm[hbase + kp + 1] = h1;
            sm[lbase + kp] = l0; sm[lbase + kp + 1] = l1;
        }
    };

    ldchunk(0);
    stage(0);
    ldchunk(1);
    __syncthreads();

    // ---- mma mainloop: warp w owns rows [16w,16w+16), all 5 n-tiles -------
    float acc[5][4];
#pragma unroll
    for (int nt = 0; nt < 5; nt++)
#pragma unroll
        for (int i = 0; i < 4; i++) acc[nt][i] = 0.f;

    const int r0 = w * 16;
    const uint32_t aoff0 = (r0 + g) * SA + tig;        // + buf base + s*8
    const uint32_t aoff1 = (r0 + g + 8) * SA + tig;

    for (int c = 0; c < 8; c++) {
        int b = c & 1;
        uint32_t hb = (b ? A_H1 : A_H0), lb = (b ? A_L1 : A_L0);
#pragma unroll
        for (int s = 0; s < 2; s++) {
            uint32_t o0 = s * 8 + aoff0, o1 = s * 8 + aoff1;
            uint32_t a0h = sm[hb + o0], a1h = sm[hb + o1];
            uint32_t a2h = sm[hb + o0 + 4], a3h = sm[hb + o1 + 4];
            uint32_t a0l = sm[lb + o0], a1l = sm[lb + o1];
            uint32_t a2l = sm[lb + o0 + 4], a3l = sm[lb + o1 + 4];
            int kpg = c * 16 + s * 8 + tig;
#pragma unroll
            for (int nt = 0; nt < 5; nt++) {
                uint32_t bo_ = (nt * 8 + g) * SB + kpg;
                uint32_t b0h = sm[B_H + bo_], b1h = sm[B_H + bo_ + 4];
                uint32_t b0l = sm[B_L + bo_], b1l = sm[B_L + bo_ + 4];
                mma16816(acc[nt][0], acc[nt][1], acc[nt][2], acc[nt][3],
                         a0h, a1h, a2h, a3h, b0h, b1h);
                mma16816(acc[nt][0], acc[nt][1], acc[nt][2], acc[nt][3],
                         a0h, a1h, a2h, a3h, b0l, b1l);
                mma16816(acc[nt][0], acc[nt][1], acc[nt][2], acc[nt][3],
                         a0l, a1l, a2l, a3l, b0h, b1h);
            }
        }
        if (c < 7) {
            stage(1 - b);                 // store prefetched chunk c+1
            if (c < 6) ldchunk(c + 2);    // gmem loads for chunk c+2
        }
        __syncthreads();
    }

    // ---- epilogue: D -> smem logits [128][41], per-row softmax ------------
    float* lg = (float*)sm;               // aliases dead A buffers (needs 5248 words)
#pragma unroll
    for (int nt = 0; nt < 5; nt++) {
        int col = nt * 8 + 2 * tig;
        lg[(r0 + g) * 41 + col]         = acc[nt][0];
        lg[(r0 + g) * 41 + col + 1]     = acc[nt][1];
        lg[(r0 + g + 8) * 41 + col]     = acc[nt][2];
        lg[(r0 + g + 8) * 41 + col + 1] = acc[nt][3];
    }
    __syncthreads();

    if (t < nrows) {
        const float* Lr = lg + t * 41;
        int orig = rowidx[t];
        float L[NCOL];
#pragma unroll
        for (int j = 0; j < NCOL; j++) L[j] = Lr[j] + biasz[j];

        float m1 = L[0];
#pragma unroll
        for (int j = 1; j < 16; j++) m1 = fmaxf(m1, L[j]);
        float s1 = 0.f;
#pragma unroll
        for (int j = 0; j < 16; j++) s1 += expf(L[j] - m1);
        float p1 = expf(L[phase] - m1) / s1;

        float m2 = L[16];
#pragma unroll
        for (int j = 17; j < 24; j++) m2 = fmaxf(m2, L[j]);
        float s2 = 0.f;
#pragma unroll
        for (int j = 16; j < 24; j++) s2 += expf(L[j] - m2);
        float p2 = expf(L[16 + occl] - m2) / s2;

        int sj = subj[orig];
        float m3 = L[24];
#pragma unroll
        for (int j = 25; j < 40; j++) m3 = fmaxf(m3, L[j]);
        float s3 = 0.f;
#pragma unroll
        for (int j = 24; j < 40; j++) s3 += expf(L[j] - m3);
        float p3 = expf(L[24 + sj] - m3) / s3;

        float po = p1 * p2;
        out[orig]         = p1;
        out[n + orig]     = po;
        out[2 * n + orig] = po * p3;
    }
}

// ---------------------------------------------------------------------------
extern "C" void kernel_launch(void* const* d_in, const int* in_sizes, int n_in,
                              void* d_out, int out_size) {
    const float* X  = (const float*)d_in[0];
    const float* Wp = (const float*)d_in[1];
    const float* bp = (const float*)d_in[2];
    const float* Wo = (const float*)d_in[3];
    const float* bo = (const float*)d_in[4];
    const float* Ws = (const float*)d_in[5];
    const float* bs = (const float*)d_in[6];
    const int*   xp = (const int*)d_in[7];
    const int*   xo = (const int*)d_in[8];
    const int*   xs = (const int*)d_in[9];
    int n = in_sizes[0] / HDIM;
    float* out = (float*)d_out;

    static int cfg = 0;
    if (!cfg) {
        cudaFuncSetAttribute(k_main, cudaFuncAttributeMaxDynamicSharedMemorySize,
                             DSM_WORDS * 4);
        cfg = 1;
    }

    k_zero<<<1, 128>>>();
    k_scatter<<<(n + 1023) / 1024, 256>>>(xp, xo, n);
    dim3 grid(NBIN, CAP / MT);
    k_main<<<grid, 256, DSM_WORDS * 4>>>(X, Wp, bp, Wo, bo, Ws, bs, xs, out, n);
}